// round 6
// baseline (speedup 1.0000x reference)
#include <cuda_runtime.h>
#include <cuda_bf16.h>

// Problem constants
#define B   4
#define N   1024
#define H   8
#define D   256
#define L   4
#define DK  32
#define SVD 16
#define NSP 512
#define EPS 1e-6f

#define BND (B * N * D)   // 1048576
#define ND  (N * D)       // 262144
#define DD  (D * D)       // 65536

// ---------------------------------------------------------------------------
// Scratch (device globals; allocation-free per harness rules)
// ---------------------------------------------------------------------------
__device__ float g_node_add[ND];
__device__ float g_q[BND];
__device__ float g_k[BND];
__device__ float g_v[BND];
__device__ float g_o[BND];
__device__ float g_f[BND];
__device__ float g_tmp[BND];

// ---------------------------------------------------------------------------
// Kernel 0: per-node additive embedding:
//   node_add[n,d] = in_deg_emb[in_deg[n],d] + out_deg_emb[out_deg[n],d]
//                 + b_svd[d] + sum_j pos[n,j] * W_svd[j,d]
//   with pos = concat(svd[:, :16], -svd[:, 16:])
// ---------------------------------------------------------------------------
__global__ void k_node_pre(const int* __restrict__ in_deg,
                           const int* __restrict__ out_deg,
                           const float* __restrict__ in_emb,
                           const float* __restrict__ out_emb,
                           const float* __restrict__ svd,
                           const float* __restrict__ Wsvd,
                           const float* __restrict__ bsvd)
{
    int idx = blockIdx.x * blockDim.x + threadIdx.x;
    if (idx >= ND) return;
    int n = idx >> 8;          // / D
    int d = idx & (D - 1);     // % D
    float val = in_emb[in_deg[n] * D + d] + out_emb[out_deg[n] * D + d] + bsvd[d];
#pragma unroll
    for (int j = 0; j < SVD; j++)
        val += svd[n * (2 * SVD) + j] * Wsvd[j * D + d];
#pragma unroll
    for (int j = SVD; j < 2 * SVD; j++)
        val -= svd[n * (2 * SVD) + j] * Wsvd[j * D + d];
    g_node_add[idx] = val;
}

// h[b,n,d] = x[b,n,d] + node_add[n,d]
__global__ void k_add_node(const float* __restrict__ x, float* __restrict__ h)
{
    int idx = blockIdx.x * blockDim.x + threadIdx.x;
    if (idx >= BND) return;
    h[idx] = x[idx] + g_node_add[idx & (ND - 1)];
}

// ---------------------------------------------------------------------------
// Tiled fp32 GEMM: C[M,256] = A[M,256] @ W[256,256] + bias (+ resid) (relu?)
// 64x64 block tile, 16x16 threads, 4x4 register micro-tile, BK=16
// ---------------------------------------------------------------------------
#define BM 64
#define BN 64
#define BK 16

__global__ __launch_bounds__(256)
void k_gemm(const float* __restrict__ A, const float* __restrict__ W,
            const float* __restrict__ bias, const float* __restrict__ resid,
            float* __restrict__ C, int relu)
{
    __shared__ float As[BK][BM + 1];   // +1 pad: conflict-free transposed store
    __shared__ float Bs[BK][BN];

    int tid = threadIdx.x;
    int tx = tid & 15;        // 0..15 -> col group
    int ty = tid >> 4;        // 0..15 -> row group
    int brow = blockIdx.y * BM;
    int bcol = blockIdx.x * BN;

    float acc[4][4] = {};

    for (int k0 = 0; k0 < D; k0 += BK) {
        // load A tile (64 x 16), store transposed
#pragma unroll
        for (int i = tid; i < BM * BK; i += 256) {
            int r = i >> 4;            // /BK
            int c = i & (BK - 1);
            As[c][r] = A[(brow + r) * D + k0 + c];
        }
        // load W tile (16 x 64)
#pragma unroll
        for (int i = tid; i < BK * BN; i += 256) {
            int r = i >> 6;            // /BN
            int c = i & (BN - 1);
            Bs[r][c] = W[(k0 + r) * D + bcol + c];
        }
        __syncthreads();
#pragma unroll
        for (int kk = 0; kk < BK; kk++) {
            float a[4], b[4];
#pragma unroll
            for (int i = 0; i < 4; i++) a[i] = As[kk][ty * 4 + i];
#pragma unroll
            for (int j = 0; j < 4; j++) b[j] = Bs[kk][tx * 4 + j];
#pragma unroll
            for (int i = 0; i < 4; i++)
#pragma unroll
                for (int j = 0; j < 4; j++)
                    acc[i][j] += a[i] * b[j];
        }
        __syncthreads();
    }

#pragma unroll
    for (int i = 0; i < 4; i++) {
        int row = brow + ty * 4 + i;
#pragma unroll
        for (int j = 0; j < 4; j++) {
            int col = bcol + tx * 4 + j;
            float v = acc[i][j] + bias[col];
            if (resid) v += resid[row * D + col];
            if (relu) v = fmaxf(v, 0.0f);
            C[row * D + col] = v;
        }
    }
}

// ---------------------------------------------------------------------------
// Attention: one block (128 thr) per (b, h, q).
// q/k/v layout: [B,N,D] with head h occupying floats [h*32, h*32+32)
// ---------------------------------------------------------------------------
__global__ __launch_bounds__(128)
void k_attn(const float* __restrict__ q, const float* __restrict__ k,
            const float* __restrict__ v,
            const int* __restrict__ spatial_pos,
            const float* __restrict__ spatial_emb,
            float* __restrict__ o)
{
    __shared__ float qv[DK];
    __shared__ float srow[N];
    __shared__ float red[4];
    __shared__ float opart[4][DK];

    int tid  = threadIdx.x;
    int lane = tid & 31;
    int wid  = tid >> 5;

    int qi = blockIdx.x & (N - 1);
    int h  = (blockIdx.x >> 10) & (H - 1);
    int b  = blockIdx.x >> 13;

    const float scale = 0.17677669529663687f;  // 1/sqrt(32)

    if (tid < DK) qv[tid] = q[((b * N + qi) * D) + h * DK + tid];
    __syncthreads();

    // phase 1: scores + local max
    float lmax = -1e30f;
    for (int kk = tid; kk < N; kk += 128) {
        const float4* k4 = (const float4*)(k + ((b * N + kk) * D) + h * DK);
        const float4* q4 = (const float4*)qv;
        float s = 0.0f;
#pragma unroll
        for (int d4 = 0; d4 < 8; d4++) {
            float4 kvv = k4[d4];
            float4 qvv = q4[d4];
            s += kvv.x * qvv.x + kvv.y * qvv.y + kvv.z * qvv.z + kvv.w * qvv.w;
        }
        int sp = spatial_pos[qi * N + kk];
        s = s * scale + spatial_emb[sp * H + h];
        srow[kk] = s;
        lmax = fmaxf(lmax, s);
    }
#pragma unroll
    for (int off = 16; off; off >>= 1)
        lmax = fmaxf(lmax, __shfl_xor_sync(0xffffffffu, lmax, off));
    if (lane == 0) red[wid] = lmax;
    __syncthreads();
    float gmax = fmaxf(fmaxf(red[0], red[1]), fmaxf(red[2], red[3]));
    __syncthreads();

    // phase 2: exp + sum
    float lsum = 0.0f;
    for (int kk = tid; kk < N; kk += 128) {
        float e = __expf(srow[kk] - gmax);
        srow[kk] = e;
        lsum += e;
    }
#pragma unroll
    for (int off = 16; off; off >>= 1)
        lsum += __shfl_xor_sync(0xffffffffu, lsum, off);
    if (lane == 0) red[wid] = lsum;
    __syncthreads();
    float inv = 1.0f / (red[0] + red[1] + red[2] + red[3]);

    // phase 3: AV. thread -> (chunk of 256 k's, one dk). Coalesced V loads.
    int dk    = tid & (DK - 1);
    int chunk = tid >> 5;          // 0..3
    float acc = 0.0f;
    int kbase = chunk * 256;
    const float* vb = v + (b * N + kbase) * D + h * DK + dk;
#pragma unroll 4
    for (int kk = 0; kk < 256; kk++)
        acc += srow[kbase + kk] * vb[kk * D];
    opart[chunk][dk] = acc;
    __syncthreads();

    if (tid < DK) {
        float r = (opart[0][tid] + opart[1][tid] + opart[2][tid] + opart[3][tid]) * inv;
        o[((b * N + qi) * D) + h * DK + tid] = r;
    }
}

// ---------------------------------------------------------------------------
// LayerNorm over last dim (D=256); one block (256 thr) per row.
// ---------------------------------------------------------------------------
__global__ __launch_bounds__(256)
void k_ln(const float* __restrict__ in, const float* __restrict__ g,
          const float* __restrict__ bb, float* __restrict__ out)
{
    __shared__ float red[8];
    int row = blockIdx.x;
    int tid = threadIdx.x;
    int lane = tid & 31;
    int wid = tid >> 5;

    float v = in[row * D + tid];

    float s = v;
#pragma unroll
    for (int off = 16; off; off >>= 1) s += __shfl_xor_sync(0xffffffffu, s, off);
    if (lane == 0) red[wid] = s;
    __syncthreads();
    if (tid == 0) {
        float t = 0.0f;
#pragma unroll
        for (int i = 0; i < 8; i++) t += red[i];
        red[0] = t * (1.0f / D);
    }
    __syncthreads();
    float mu = red[0];
    __syncthreads();

    float dv = v - mu;
    float s2 = dv * dv;
#pragma unroll
    for (int off = 16; off; off >>= 1) s2 += __shfl_xor_sync(0xffffffffu, s2, off);
    if (lane == 0) red[wid] = s2;
    __syncthreads();
    if (tid == 0) {
        float t = 0.0f;
#pragma unroll
        for (int i = 0; i < 8; i++) t += red[i];
        red[0] = rsqrtf(t * (1.0f / D) + EPS);
    }
    __syncthreads();
    float rstd = red[0];

    out[row * D + tid] = dv * rstd * g[tid] + bb[tid];
}

// ---------------------------------------------------------------------------
// Launch
// ---------------------------------------------------------------------------
extern "C" void kernel_launch(void* const* d_in, const int* in_sizes, int n_in,
                              void* d_out, int out_size)
{
    // Two possible input orderings:
    //  (a) setup_inputs() dict-insertion order:
    //      x, in_degrees, out_degrees, spatial_pos, svd_emb, in_deg_emb,
    //      out_deg_emb, spatial_emb, W_svd, b_svd, Wq, Wk, Wv, Wa, W1, W2,
    //      bq, bk, bv, ba, b1, b2, ln1_b, ln2_b, ln1_g, ln2_g
    //  (b) reference() signature order:
    //      x, svd_emb, W_svd, b_svd, in_deg_emb, out_deg_emb, spatial_emb,
    //      Wq, bq, Wk, bk, Wv, bv, Wa, ba, ln1_g, ln1_b, W1, b1, W2, b2,
    //      ln2_g, ln2_b, in_degrees, out_degrees, spatial_pos
    // Discriminate by in_sizes[1]: (a) -> 1024 (in_degrees); (b) -> 32768 (svd_emb).
    const float *x, *svd_emb, *W_svd, *b_svd, *in_emb, *out_emb, *sp_emb;
    const float *Wq, *bq, *Wk, *bk, *Wv, *bv, *Wa, *ba;
    const float *ln1_g, *ln1_b, *W1, *b1, *W2, *b2, *ln2_g, *ln2_b;
    const int *in_deg, *out_deg, *sp_pos;

    if (in_sizes[1] == N) {
        // setup order
        x       = (const float*)d_in[0];
        in_deg  = (const int*)  d_in[1];
        out_deg = (const int*)  d_in[2];
        sp_pos  = (const int*)  d_in[3];
        svd_emb = (const float*)d_in[4];
        in_emb  = (const float*)d_in[5];
        out_emb = (const float*)d_in[6];
        sp_emb  = (const float*)d_in[7];
        W_svd   = (const float*)d_in[8];
        b_svd   = (const float*)d_in[9];
        Wq = (const float*)d_in[10];
        Wk = (const float*)d_in[11];
        Wv = (const float*)d_in[12];
        Wa = (const float*)d_in[13];
        W1 = (const float*)d_in[14];
        W2 = (const float*)d_in[15];
        bq = (const float*)d_in[16];
        bk = (const float*)d_in[17];
        bv = (const float*)d_in[18];
        ba = (const float*)d_in[19];
        b1 = (const float*)d_in[20];
        b2 = (const float*)d_in[21];
        ln1_b = (const float*)d_in[22];
        ln2_b = (const float*)d_in[23];
        ln1_g = (const float*)d_in[24];
        ln2_g = (const float*)d_in[25];
    } else {
        // signature order
        x       = (const float*)d_in[0];
        svd_emb = (const float*)d_in[1];
        W_svd   = (const float*)d_in[2];
        b_svd   = (const float*)d_in[3];
        in_emb  = (const float*)d_in[4];
        out_emb = (const float*)d_in[5];
        sp_emb  = (const float*)d_in[6];
        Wq = (const float*)d_in[7];
        bq = (const float*)d_in[8];
        Wk = (const float*)d_in[9];
        bk = (const float*)d_in[10];
        Wv = (const float*)d_in[11];
        bv = (const float*)d_in[12];
        Wa = (const float*)d_in[13];
        ba = (const float*)d_in[14];
        ln1_g = (const float*)d_in[15];
        ln1_b = (const float*)d_in[16];
        W1 = (const float*)d_in[17];
        b1 = (const float*)d_in[18];
        W2 = (const float*)d_in[19];
        b2 = (const float*)d_in[20];
        ln2_g = (const float*)d_in[21];
        ln2_b = (const float*)d_in[22];
        in_deg  = (const int*)d_in[23];
        out_deg = (const int*)d_in[24];
        sp_pos  = (const int*)d_in[25];
    }

    float* h = (float*)d_out;   // residual stream lives in d_out

    float *q, *k, *v, *o, *f, *tmp;
    cudaGetSymbolAddress((void**)&q,   g_q);
    cudaGetSymbolAddress((void**)&k,   g_k);
    cudaGetSymbolAddress((void**)&v,   g_v);
    cudaGetSymbolAddress((void**)&o,   g_o);
    cudaGetSymbolAddress((void**)&f,   g_f);
    cudaGetSymbolAddress((void**)&tmp, g_tmp);

    // preamble
    k_node_pre<<<ND / 256, 256>>>(in_deg, out_deg, in_emb, out_emb,
                                  svd_emb, W_svd, b_svd);
    k_add_node<<<BND / 256, 256>>>(x, h);

    dim3 ggrid(D / BN, (B * N) / BM);   // (4, 64)

    for (int l = 0; l < L; l++) {
        const float* wq = Wq + l * DD; const float* bql = bq + l * D;
        const float* wk = Wk + l * DD; const float* bkl = bk + l * D;
        const float* wv = Wv + l * DD; const float* bvl = bv + l * D;
        const float* wa = Wa + l * DD; const float* bal = ba + l * D;
        const float* w1 = W1 + l * DD; const float* b1l = b1 + l * D;
        const float* w2 = W2 + l * DD; const float* b2l = b2 + l * D;

        k_gemm<<<ggrid, 256>>>(h, wq, bql, nullptr, q, 0);
        k_gemm<<<ggrid, 256>>>(h, wk, bkl, nullptr, k, 0);
        k_gemm<<<ggrid, 256>>>(h, wv, bvl, nullptr, v, 0);

        k_attn<<<B * H * N, 128>>>(q, k, v, sp_pos, sp_emb, o);

        // tmp = h + o @ Wa + ba ; h = LN1(tmp)
        k_gemm<<<ggrid, 256>>>(o, wa, bal, h, tmp, 0);
        k_ln<<<B * N, 256>>>(tmp, ln1_g + l * D, ln1_b + l * D, h);

        // f = relu(h @ W1 + b1); tmp = h + f @ W2 + b2 ; h = LN2(tmp)
        k_gemm<<<ggrid, 256>>>(h, w1, b1l, nullptr, f, 1);
        k_gemm<<<ggrid, 256>>>(f, w2, b2l, h, tmp, 0);
        k_ln<<<B * N, 256>>>(tmp, ln2_g + l * D, ln2_b + l * D, h);
    }
}

// round 7
// speedup vs baseline: 3.6950x; 3.6950x over previous
#include <cuda_runtime.h>
#include <cuda_bf16.h>

// Problem constants
#define B   4
#define N   1024
#define H   8
#define D   256
#define L   4
#define DK  32
#define SVD 16
#define NSP 512
#define EPS 1e-6f

#define BND (B * N * D)   // 1048576
#define ND  (N * D)       // 262144
#define DD  (D * D)       // 65536

// ---------------------------------------------------------------------------
// Scratch (device globals; allocation-free per harness rules)
// ---------------------------------------------------------------------------
__device__ float g_node_add[ND];
__device__ float g_q[BND];
__device__ float g_k[BND];
__device__ float g_v[BND];
__device__ float g_o[BND];
__device__ float g_f[BND];
__device__ float g_tmp[BND];
__device__ float g_bias[H * N * N];   // 33.5 MB precomputed attention bias

// ---------------------------------------------------------------------------
// bias[h][qi][kk] = spatial_emb[spatial_pos[qi][kk]][h]
// ---------------------------------------------------------------------------
__global__ void k_bias(const int* __restrict__ sp, const float* __restrict__ emb)
{
    int idx = blockIdx.x * 256 + threadIdx.x;   // over N*N
    if (idx >= N * N) return;
    int s = sp[idx];
#pragma unroll
    for (int h = 0; h < H; h++)
        g_bias[h * (N * N) + idx] = emb[s * H + h];
}

// ---------------------------------------------------------------------------
// per-node additive embedding
// ---------------------------------------------------------------------------
__global__ void k_node_pre(const int* __restrict__ in_deg,
                           const int* __restrict__ out_deg,
                           const float* __restrict__ in_emb,
                           const float* __restrict__ out_emb,
                           const float* __restrict__ svd,
                           const float* __restrict__ Wsvd,
                           const float* __restrict__ bsvd)
{
    int idx = blockIdx.x * blockDim.x + threadIdx.x;
    if (idx >= ND) return;
    int n = idx >> 8;
    int d = idx & (D - 1);
    float val = in_emb[in_deg[n] * D + d] + out_emb[out_deg[n] * D + d] + bsvd[d];
#pragma unroll
    for (int j = 0; j < SVD; j++)
        val += svd[n * (2 * SVD) + j] * Wsvd[j * D + d];
#pragma unroll
    for (int j = SVD; j < 2 * SVD; j++)
        val -= svd[n * (2 * SVD) + j] * Wsvd[j * D + d];
    g_node_add[idx] = val;
}

__global__ void k_add_node(const float* __restrict__ x, float* __restrict__ h)
{
    int idx = blockIdx.x * blockDim.x + threadIdx.x;
    if (idx >= BND) return;
    h[idx] = x[idx] + g_node_add[idx & (ND - 1)];
}

// ---------------------------------------------------------------------------
// Tiled fp32 GEMM (64x64 tile, 4x4 micro-tile, float4 staged loads)
// ---------------------------------------------------------------------------
#define BM 64
#define BN 64
#define BK 16

__device__ __forceinline__
void gemm_body(const float* __restrict__ A, const float* __restrict__ W,
               const float* __restrict__ bias, const float* __restrict__ resid,
               float* __restrict__ C, int relu, int brow, int bcol)
{
    __shared__ float As[BK][BM + 1];
    __shared__ float Bs[BK][BN];

    int tid = threadIdx.x;
    int tx = tid & 15;
    int ty = tid >> 4;

    float acc[4][4] = {};

    for (int k0 = 0; k0 < D; k0 += BK) {
        {   // A tile 64x16: one float4 per thread
            int r  = tid >> 2;
            int c4 = (tid & 3) * 4;
            float4 av = *(const float4*)(A + (size_t)(brow + r) * D + k0 + c4);
            As[c4 + 0][r] = av.x; As[c4 + 1][r] = av.y;
            As[c4 + 2][r] = av.z; As[c4 + 3][r] = av.w;
            // W tile 16x64: one float4 per thread
            int r2 = tid >> 4;
            int c2 = (tid & 15) * 4;
            *(float4*)&Bs[r2][c2] = *(const float4*)(W + (size_t)(k0 + r2) * D + bcol + c2);
        }
        __syncthreads();
#pragma unroll
        for (int kk = 0; kk < BK; kk++) {
            float a[4], b[4];
#pragma unroll
            for (int i = 0; i < 4; i++) a[i] = As[kk][ty * 4 + i];
#pragma unroll
            for (int j = 0; j < 4; j++) b[j] = Bs[kk][tx * 4 + j];
#pragma unroll
            for (int i = 0; i < 4; i++)
#pragma unroll
                for (int j = 0; j < 4; j++)
                    acc[i][j] += a[i] * b[j];
        }
        __syncthreads();
    }

#pragma unroll
    for (int i = 0; i < 4; i++) {
        int row = brow + ty * 4 + i;
#pragma unroll
        for (int j = 0; j < 4; j++) {
            int col = bcol + tx * 4 + j;
            float v = acc[i][j] + bias[col];
            if (resid) v += resid[(size_t)row * D + col];
            if (relu) v = fmaxf(v, 0.0f);
            C[(size_t)row * D + col] = v;
        }
    }
}

__global__ __launch_bounds__(256)
void k_gemm(const float* __restrict__ A, const float* __restrict__ W,
            const float* __restrict__ bias, const float* __restrict__ resid,
            float* __restrict__ C, int relu)
{
    gemm_body(A, W, bias, resid, C, relu, blockIdx.y * BM, blockIdx.x * BN);
}

// fused QKV: blockIdx.z selects (W, bias, out)
__global__ __launch_bounds__(256)
void k_gemm_qkv(const float* __restrict__ A,
                const float* __restrict__ W0, const float* __restrict__ W1,
                const float* __restrict__ W2,
                const float* __restrict__ b0, const float* __restrict__ b1,
                const float* __restrict__ b2,
                float* __restrict__ C0, float* __restrict__ C1,
                float* __restrict__ C2)
{
    const float* W = (blockIdx.z == 0) ? W0 : (blockIdx.z == 1) ? W1 : W2;
    const float* bb = (blockIdx.z == 0) ? b0 : (blockIdx.z == 1) ? b1 : b2;
    float* C = (blockIdx.z == 0) ? C0 : (blockIdx.z == 1) ? C1 : C2;
    gemm_body(A, W, bb, nullptr, C, 0, blockIdx.y * BM, blockIdx.x * BN);
}

// ---------------------------------------------------------------------------
// Flash-style attention: one block (256 thr) per (b, h, 64-q tile).
// Online softmax; K/V tiles of 64 staged in smem.
// ---------------------------------------------------------------------------
#define QT 64
#define KT 64

__global__ __launch_bounds__(256)
void k_attn2(const float* __restrict__ q, const float* __restrict__ k,
             const float* __restrict__ v, float* __restrict__ o)
{
    __shared__ float Qs[DK][QT];        // scaled, transposed Q
    __shared__ float Kst[DK][KT + 1];   // transposed K tile
    __shared__ float Vs[KT][36];        // padded V tile
    __shared__ float Ps[QT][72];        // probabilities, float4-aligned stride
    __shared__ float cfac[QT];
    __shared__ float lrow[QT];

    int tid = threadIdx.x;
    int bid = blockIdx.x;
    int qt = bid & (N / QT - 1);        // 16
    int h  = (bid >> 4) & (H - 1);
    int b  = bid >> 7;
    int q0 = qt * QT;

    const float scale = 0.17677669529663687f;  // 1/sqrt(32)

    // load Q tile, pre-scaled, transposed
    {
        int e = tid;
#pragma unroll
        for (int it = 0; it < 2; it++, e += 256) {
            int r  = e >> 3;
            int dg = (e & 7) * 4;
            float4 qv = *(const float4*)(q + (size_t)(b * N + q0 + r) * D + h * DK + dg);
            Qs[dg + 0][r] = qv.x * scale;
            Qs[dg + 1][r] = qv.y * scale;
            Qs[dg + 2][r] = qv.z * scale;
            Qs[dg + 3][r] = qv.w * scale;
        }
    }

    int tx  = tid & 15, ty  = tid >> 4;   // scores: 4q x 4k micro-tile
    int tx3 = tid & 7,  ty3 = tid >> 3;   // AV: 2q x 4d micro-tile

    float m[4], l[4];
#pragma unroll
    for (int i = 0; i < 4; i++) { m[i] = -1e30f; l[i] = 0.0f; }
    float acc[2][4] = {};

    const float* bias_h = g_bias + (size_t)h * N * N;

    for (int k0 = 0; k0 < N; k0 += KT) {
        __syncthreads();
        {   // stage K (transposed) and V tiles
            int e = tid;
#pragma unroll
            for (int it = 0; it < 2; it++, e += 256) {
                int r  = e >> 3;
                int dg = (e & 7) * 4;
                const float* kp = k + (size_t)(b * N + k0 + r) * D + h * DK + dg;
                float4 kv = *(const float4*)kp;
                Kst[dg + 0][r] = kv.x; Kst[dg + 1][r] = kv.y;
                Kst[dg + 2][r] = kv.z; Kst[dg + 3][r] = kv.w;
                const float* vp = v + (size_t)(b * N + k0 + r) * D + h * DK + dg;
                *(float4*)&Vs[r][dg] = *(const float4*)vp;
            }
        }
        __syncthreads();

        // scores with bias init
        float S[4][4];
#pragma unroll
        for (int i = 0; i < 4; i++) {
            float4 bv = *(const float4*)(bias_h + (size_t)(q0 + ty * 4 + i) * N + k0 + tx * 4);
            S[i][0] = bv.x; S[i][1] = bv.y; S[i][2] = bv.z; S[i][3] = bv.w;
        }
#pragma unroll
        for (int d = 0; d < DK; d++) {
            float4 a4 = *(const float4*)&Qs[d][ty * 4];
            float bb[4];
#pragma unroll
            for (int j = 0; j < 4; j++) bb[j] = Kst[d][tx * 4 + j];
            S[0][0] += a4.x * bb[0]; S[0][1] += a4.x * bb[1];
            S[0][2] += a4.x * bb[2]; S[0][3] += a4.x * bb[3];
            S[1][0] += a4.y * bb[0]; S[1][1] += a4.y * bb[1];
            S[1][2] += a4.y * bb[2]; S[1][3] += a4.y * bb[3];
            S[2][0] += a4.z * bb[0]; S[2][1] += a4.z * bb[1];
            S[2][2] += a4.z * bb[2]; S[2][3] += a4.z * bb[3];
            S[3][0] += a4.w * bb[0]; S[3][1] += a4.w * bb[1];
            S[3][2] += a4.w * bb[2]; S[3][3] += a4.w * bb[3];
        }

        // online softmax per q row (16-lane groups; deterministic)
#pragma unroll
        for (int i = 0; i < 4; i++) {
            float tm = fmaxf(fmaxf(S[i][0], S[i][1]), fmaxf(S[i][2], S[i][3]));
#pragma unroll
            for (int off = 8; off; off >>= 1)
                tm = fmaxf(tm, __shfl_xor_sync(0xffffffffu, tm, off));
            float mn = fmaxf(m[i], tm);
            float c  = __expf(m[i] - mn);
            m[i] = mn;
            float4 p4;
            p4.x = __expf(S[i][0] - mn);
            p4.y = __expf(S[i][1] - mn);
            p4.z = __expf(S[i][2] - mn);
            p4.w = __expf(S[i][3] - mn);
            float ps = p4.x + p4.y + p4.z + p4.w;
#pragma unroll
            for (int off = 8; off; off >>= 1)
                ps += __shfl_xor_sync(0xffffffffu, ps, off);
            l[i] = l[i] * c + ps;
            if (tx == 0) cfac[ty * 4 + i] = c;
            *(float4*)&Ps[ty * 4 + i][tx * 4] = p4;
        }
        __syncthreads();

        // AV accumulate: q pair = ty3*2, d quad = tx3*4
        {
            int qa = ty3 * 2;
            float c0 = cfac[qa], c1 = cfac[qa + 1];
#pragma unroll
            for (int j = 0; j < 4; j++) { acc[0][j] *= c0; acc[1][j] *= c1; }
#pragma unroll 4
            for (int kk = 0; kk < KT; kk++) {
                float a0 = Ps[qa][kk];
                float a1 = Ps[qa + 1][kk];
                float4 b4 = *(const float4*)&Vs[kk][tx3 * 4];
                acc[0][0] += a0 * b4.x; acc[0][1] += a0 * b4.y;
                acc[0][2] += a0 * b4.z; acc[0][3] += a0 * b4.w;
                acc[1][0] += a1 * b4.x; acc[1][1] += a1 * b4.y;
                acc[1][2] += a1 * b4.z; acc[1][3] += a1 * b4.w;
            }
        }
    }

    // publish row sums, normalize, write out
    if (tx == 0) {
#pragma unroll
        for (int i = 0; i < 4; i++) lrow[ty * 4 + i] = l[i];
    }
    __syncthreads();
    {
        int qa = ty3 * 2;
        float inv0 = 1.0f / lrow[qa];
        float inv1 = 1.0f / lrow[qa + 1];
        float4 o0, o1;
        o0.x = acc[0][0] * inv0; o0.y = acc[0][1] * inv0;
        o0.z = acc[0][2] * inv0; o0.w = acc[0][3] * inv0;
        o1.x = acc[1][0] * inv1; o1.y = acc[1][1] * inv1;
        o1.z = acc[1][2] * inv1; o1.w = acc[1][3] * inv1;
        *(float4*)(o + (size_t)(b * N + q0 + qa) * D + h * DK + tx3 * 4)     = o0;
        *(float4*)(o + (size_t)(b * N + q0 + qa + 1) * D + h * DK + tx3 * 4) = o1;
    }
}

// ---------------------------------------------------------------------------
// LayerNorm over last dim (D=256); one block (256 thr) per row.
// ---------------------------------------------------------------------------
__global__ __launch_bounds__(256)
void k_ln(const float* __restrict__ in, const float* __restrict__ g,
          const float* __restrict__ bb, float* __restrict__ out)
{
    __shared__ float red[8];
    int row = blockIdx.x;
    int tid = threadIdx.x;
    int lane = tid & 31;
    int wid = tid >> 5;

    float v = in[(size_t)row * D + tid];

    float s = v;
#pragma unroll
    for (int off = 16; off; off >>= 1) s += __shfl_xor_sync(0xffffffffu, s, off);
    if (lane == 0) red[wid] = s;
    __syncthreads();
    if (tid == 0) {
        float t = 0.0f;
#pragma unroll
        for (int i = 0; i < 8; i++) t += red[i];
        red[0] = t * (1.0f / D);
    }
    __syncthreads();
    float mu = red[0];
    __syncthreads();

    float dv = v - mu;
    float s2 = dv * dv;
#pragma unroll
    for (int off = 16; off; off >>= 1) s2 += __shfl_xor_sync(0xffffffffu, s2, off);
    if (lane == 0) red[wid] = s2;
    __syncthreads();
    if (tid == 0) {
        float t = 0.0f;
#pragma unroll
        for (int i = 0; i < 8; i++) t += red[i];
        red[0] = rsqrtf(t * (1.0f / D) + EPS);
    }
    __syncthreads();
    float rstd = red[0];

    out[(size_t)row * D + tid] = dv * rstd * g[tid] + bb[tid];
}

// ---------------------------------------------------------------------------
// Launch
// ---------------------------------------------------------------------------
extern "C" void kernel_launch(void* const* d_in, const int* in_sizes, int n_in,
                              void* d_out, int out_size)
{
    const float *x, *svd_emb, *W_svd, *b_svd, *in_emb, *out_emb, *sp_emb;
    const float *Wq, *bq, *Wk, *bk, *Wv, *bv, *Wa, *ba;
    const float *ln1_g, *ln1_b, *W1, *b1, *W2, *b2, *ln2_g, *ln2_b;
    const int *in_deg, *out_deg, *sp_pos;

    if (in_sizes[1] == N) {
        // setup_inputs() dict order
        x       = (const float*)d_in[0];
        in_deg  = (const int*)  d_in[1];
        out_deg = (const int*)  d_in[2];
        sp_pos  = (const int*)  d_in[3];
        svd_emb = (const float*)d_in[4];
        in_emb  = (const float*)d_in[5];
        out_emb = (const float*)d_in[6];
        sp_emb  = (const float*)d_in[7];
        W_svd   = (const float*)d_in[8];
        b_svd   = (const float*)d_in[9];
        Wq = (const float*)d_in[10];
        Wk = (const float*)d_in[11];
        Wv = (const float*)d_in[12];
        Wa = (const float*)d_in[13];
        W1 = (const float*)d_in[14];
        W2 = (const float*)d_in[15];
        bq = (const float*)d_in[16];
        bk = (const float*)d_in[17];
        bv = (const float*)d_in[18];
        ba = (const float*)d_in[19];
        b1 = (const float*)d_in[20];
        b2 = (const float*)d_in[21];
        ln1_b = (const float*)d_in[22];
        ln2_b = (const float*)d_in[23];
        ln1_g = (const float*)d_in[24];
        ln2_g = (const float*)d_in[25];
    } else {
        // reference() signature order
        x       = (const float*)d_in[0];
        svd_emb = (const float*)d_in[1];
        W_svd   = (const float*)d_in[2];
        b_svd   = (const float*)d_in[3];
        in_emb  = (const float*)d_in[4];
        out_emb = (const float*)d_in[5];
        sp_emb  = (const float*)d_in[6];
        Wq = (const float*)d_in[7];
        bq = (const float*)d_in[8];
        Wk = (const float*)d_in[9];
        bk = (const float*)d_in[10];
        Wv = (const float*)d_in[11];
        bv = (const float*)d_in[12];
        Wa = (const float*)d_in[13];
        ba = (const float*)d_in[14];
        ln1_g = (const float*)d_in[15];
        ln1_b = (const float*)d_in[16];
        W1 = (const float*)d_in[17];
        b1 = (const float*)d_in[18];
        W2 = (const float*)d_in[19];
        b2 = (const float*)d_in[20];
        ln2_g = (const float*)d_in[21];
        ln2_b = (const float*)d_in[22];
        in_deg  = (const int*)d_in[23];
        out_deg = (const int*)d_in[24];
        sp_pos  = (const int*)d_in[25];
    }

    float* h = (float*)d_out;

    float *q, *k, *v, *o, *f, *tmp;
    cudaGetSymbolAddress((void**)&q,   g_q);
    cudaGetSymbolAddress((void**)&k,   g_k);
    cudaGetSymbolAddress((void**)&v,   g_v);
    cudaGetSymbolAddress((void**)&o,   g_o);
    cudaGetSymbolAddress((void**)&f,   g_f);
    cudaGetSymbolAddress((void**)&tmp, g_tmp);

    // preamble
    k_bias<<<(N * N) / 256, 256>>>(sp_pos, sp_emb);
    k_node_pre<<<ND / 256, 256>>>(in_deg, out_deg, in_emb, out_emb,
                                  svd_emb, W_svd, b_svd);
    k_add_node<<<BND / 256, 256>>>(x, h);

    dim3 ggrid(D / BN, (B * N) / BM);          // (4, 64)
    dim3 ggrid3(D / BN, (B * N) / BM, 3);      // fused QKV

    for (int l = 0; l < L; l++) {
        const float* wq = Wq + (size_t)l * DD; const float* bql = bq + l * D;
        const float* wk = Wk + (size_t)l * DD; const float* bkl = bk + l * D;
        const float* wv = Wv + (size_t)l * DD; const float* bvl = bv + l * D;
        const float* wa = Wa + (size_t)l * DD; const float* bal = ba + l * D;
        const float* w1 = W1 + (size_t)l * DD; const float* b1l = b1 + l * D;
        const float* w2 = W2 + (size_t)l * DD; const float* b2l = b2 + l * D;

        k_gemm_qkv<<<ggrid3, 256>>>(h, wq, wk, wv, bql, bkl, bvl, q, k, v);

        k_attn2<<<B * H * (N / QT), 256>>>(q, k, v, o);

        k_gemm<<<ggrid, 256>>>(o, wa, bal, h, tmp, 0);
        k_ln<<<B * N, 256>>>(tmp, ln1_g + l * D, ln1_b + l * D, h);

        k_gemm<<<ggrid, 256>>>(h, w1, b1l, nullptr, f, 1);
        k_gemm<<<ggrid, 256>>>(f, w2, b2l, h, tmp, 0);
        k_ln<<<B * N, 256>>>(tmp, ln2_g + l * D, ln2_b + l * D, h);
    }
}